// round 17
// baseline (speedup 1.0000x reference)
#include <cuda_runtime.h>

// SPDUnVectorize: out[b,i,j] = x[b, tri(min(i,j), max(i,j))]
// tri(i,j), i<=j: i*N - i*(i-1)/2 + (j-i)
//
// R8 structure (confirmed 238.3us / DRAM 84% / 6.66TB/s) + 2-batch software
// pipeline: each CTA handles the same tile for two consecutive batches with
// two smem buffers. Phase 1 for both batches back-to-back (2x LDG MLP, the
// off-diag direct writes interleaved), ONE barrier, then both phase-2
// transpose stores. Halves barrier count per byte, 20480 CTAs.
// Per-phase code is byte-identical to R8.

#define NMAT 256
#define DTRI (NMAT * (NMAT + 1) / 2)   // 32896
#define TB 64
#define NTILES 10
#define THREADS 256

__constant__ int c_tbi[NTILES] = {0,0,0,0,1,1,1,2,2,3};
__constant__ int c_tbj[NTILES] = {0,1,2,3,1,2,3,2,3,3};

__device__ __forceinline__ int sw(int r, int c4) {       // swizzled float4 index
    return r * 16 + (c4 ^ ((r >> 2) & 7));
}

__global__ void __launch_bounds__(THREADS)
spd_unvec_swz2(const float* __restrict__ x, float* __restrict__ out) {
    __shared__ float4 sm[2][TB * 16];     // 2 x 16 KB

    const int t    = threadIdx.x;
    const int b0   = blockIdx.y * 2;
    const int tile = blockIdx.x;
    const int bi = c_tbi[tile];
    const int bj = c_tbj[tile];
    const bool diag = (bi == bj);

    // ---- phase 1 (both batches): load packed rows, stage smem;
    //      off-diag also writes the upper tile directly (STG.128) ----
    {
        const int c4 = t & 15;        // float4 column 0..15
        const int rg = t >> 4;        // 0..15
        #pragma unroll
        for (int bb = 0; bb < 2; bb++) {
            const float* __restrict__ xr = x + (size_t)(b0 + bb) * DTRI;
            float* __restrict__ o = out + (size_t)(b0 + bb) * (NMAT * NMAT);
            #pragma unroll
            for (int k = 0; k < 4; k++) {
                const int r = rg + k * 16;
                const int i = bi * TB + r;
                const int base = i * NMAT - (i * (i - 1)) / 2 - i + bj * TB + 4 * c4;
                float4 v;
                v.x = xr[base + 0];
                v.y = xr[base + 1];
                v.z = xr[base + 2];
                v.w = xr[base + 3];
                sm[bb][sw(r, c4)] = v;
                if (!diag)
                    *reinterpret_cast<float4*>(o + i * NMAT + bj * TB + 4 * c4) = v;
            }
        }
    }
    __syncthreads();

    // ---- phase 2 (both batches): 4x4 register transpose, STG.128 ----
    {
        const int rr4 = t & 15;       // source-row group (=> output col group)
        const int cg  = t >> 4;       // source float4-col (=> output row group)
        const int scol = cg ^ (rr4 & 7);

        #pragma unroll
        for (int bb = 0; bb < 2; bb++) {
            float* __restrict__ o = out + (size_t)(b0 + bb) * (NMAT * NMAT);

            const float4 a0 = sm[bb][(4 * rr4 + 0) * 16 + scol];
            const float4 a1 = sm[bb][(4 * rr4 + 1) * 16 + scol];
            const float4 a2 = sm[bb][(4 * rr4 + 2) * 16 + scol];
            const float4 a3 = sm[bb][(4 * rr4 + 3) * 16 + scol];

            float4 t0 = make_float4(a0.x, a1.x, a2.x, a3.x);
            float4 t1 = make_float4(a0.y, a1.y, a2.y, a3.y);
            float4 t2 = make_float4(a0.z, a1.z, a2.z, a3.z);
            float4 t3 = make_float4(a0.w, a1.w, a2.w, a3.w);

            float* __restrict__ ob =
                o + (size_t)(bj * TB + 4 * cg) * NMAT + bi * TB + 4 * rr4;

            if (!diag) {
                *reinterpret_cast<float4*>(ob + 0 * NMAT) = t0;
                *reinterpret_cast<float4*>(ob + 1 * NMAT) = t1;
                *reinterpret_cast<float4*>(ob + 2 * NMAT) = t2;
                *reinterpret_cast<float4*>(ob + 3 * NMAT) = t3;
            } else {
                float4 tq[4] = {t0, t1, t2, t3};
                #pragma unroll
                for (int q = 0; q < 4; q++) {
                    const int row = 4 * cg + q;          // tile-local output row
                    const float4 d = sm[bb][row * 16 + (rr4 ^ ((row >> 2) & 7))];
                    float4 v;
                    v.x = (4 * rr4 + 0 >= row) ? d.x : tq[q].x;
                    v.y = (4 * rr4 + 1 >= row) ? d.y : tq[q].y;
                    v.z = (4 * rr4 + 2 >= row) ? d.z : tq[q].z;
                    v.w = (4 * rr4 + 3 >= row) ? d.w : tq[q].w;
                    *reinterpret_cast<float4*>(ob + q * NMAT) = v;
                }
            }
        }
    }
}

extern "C" void kernel_launch(void* const* d_in, const int* in_sizes, int n_in,
                              void* d_out, int out_size) {
    const float* x = (const float*)d_in[0];
    float* out = (float*)d_out;

    const int B = out_size / (NMAT * NMAT);   // 4096

    dim3 grid(NTILES, B / 2);                 // (10, 2048)
    spd_unvec_swz2<<<grid, THREADS>>>(x, out);
}